// round 1
// baseline (speedup 1.0000x reference)
#include <cuda_runtime.h>
#include <cuda_bf16.h>
#include <stdint.h>

// WeightsDropout: per row of [8192,1,4096] f32, zero the 2048 smallest
// entries (stable-argsort tie-break by index), softmax over survivors.
//
// One CTA per row. Row lives in registers (16 f32/thread). Exact selection
// via a 2048-bin linear-value histogram + candidate-key ranking in the
// boundary bin (key = float_bits<<12 | index, order == stable sort order
// for positive floats).

namespace {

constexpr int N        = 4096;
constexpr int KDROP    = 2048;          // int(N * 0.5)
constexpr int THREADS  = 256;
constexpr int EPT      = N / THREADS;   // 16 elements per thread
constexpr int VEC      = EPT / 4;       // 4 float4 per thread
constexpr int NBINS    = 2048;
constexpr int BPT      = NBINS / THREADS; // 8 bins per thread
constexpr int CAND_CAP = 256;           // boundary-bin capacity (Poisson(~2) tail => safe)

__global__ __launch_bounds__(THREADS, 1)
void wdrop_kernel(const float* __restrict__ in, float* __restrict__ out)
{
    __shared__ unsigned hist[NBINS];
    __shared__ unsigned long long cand[CAND_CAP];
    __shared__ unsigned cand_n;
    __shared__ float    s_red[8];
    __shared__ unsigned s_woff[8];
    __shared__ unsigned s_bin, s_rank, s_cnt;
    __shared__ float    s_max, s_inv;

    const int t    = threadIdx.x;
    const int lane = t & 31;
    const int warp = t >> 5;

    const long long row = blockIdx.x;
    const float4* __restrict__ in4  = reinterpret_cast<const float4*>(in  + row * (long long)N);
    float4*       __restrict__ out4 = reinterpret_cast<float4*>      (out + row * (long long)N);

    // ---- zero histogram / counters ----
#pragma unroll
    for (int i = 0; i < BPT; i++) hist[t * BPT + i] = 0u;
    if (t == 0) cand_n = 0u;
    __syncthreads();

    // ---- load row into registers, histogram + max ----
    float v[EPT];
#pragma unroll
    for (int j = 0; j < VEC; j++) {
        float4 x = in4[t + THREADS * j];
        v[4 * j + 0] = x.x; v[4 * j + 1] = x.y;
        v[4 * j + 2] = x.z; v[4 * j + 3] = x.w;
    }
    float vmax = -3.4e38f;
#pragma unroll
    for (int i = 0; i < EPT; i++) {
        float val = v[i];
        vmax = fmaxf(vmax, val);
        int b = (int)(val * (float)NBINS);
        b = min(b, NBINS - 1);
        b = max(b, 0);
        atomicAdd(&hist[b], 1u);
    }
#pragma unroll
    for (int o = 16; o; o >>= 1) vmax = fmaxf(vmax, __shfl_xor_sync(0xffffffffu, vmax, o));
    if (lane == 0) s_red[warp] = vmax;
    __syncthreads();   // histogram + per-warp maxes complete
    if (t == 0) {
        float m = s_red[0];
#pragma unroll
        for (int i = 1; i < 8; i++) m = fmaxf(m, s_red[i]);
        s_max = m;
    }

    // ---- scan histogram to find bin containing rank KDROP ----
    unsigned cnt8[BPT];
    unsigned local = 0;
#pragma unroll
    for (int i = 0; i < BPT; i++) { cnt8[i] = hist[t * BPT + i]; local += cnt8[i]; }
    unsigned inc = local;
#pragma unroll
    for (int o = 1; o < 32; o <<= 1) {
        unsigned nn = __shfl_up_sync(0xffffffffu, inc, o);
        if (lane >= o) inc += nn;
    }
    if (lane == 31) s_woff[warp] = inc;
    __syncthreads();
    if (t == 0) {
        unsigned acc = 0;
#pragma unroll
        for (int i = 0; i < 8; i++) { unsigned x = s_woff[i]; s_woff[i] = acc; acc += x; }
    }
    __syncthreads();
    {
        unsigned c = s_woff[warp] + inc - local;   // exclusive prefix of this thread's bin group
#pragma unroll
        for (int i = 0; i < BPT; i++) {
            unsigned cc = cnt8[i];
            if (c <= (unsigned)KDROP && (unsigned)KDROP < c + cc) {
                s_bin  = (unsigned)(t * BPT + i);
                s_rank = (unsigned)KDROP - c;   // # boundary-bin elems to drop
                s_cnt  = cc;
            }
            c += cc;
        }
    }
    __syncthreads();
    const unsigned bstar = s_bin;
    const unsigned rstar = s_rank;
    const unsigned ccnt  = min(s_cnt, (unsigned)CAND_CAP);
    const float    m     = s_max;

    // ---- gather boundary-bin candidates as (bits<<12 | idx) keys ----
#pragma unroll
    for (int i = 0; i < EPT; i++) {
        float val = v[i];
        int b = min((int)(val * (float)NBINS), NBINS - 1);
        if ((unsigned)b == bstar) {
            unsigned p = atomicAdd(&cand_n, 1u);
            if (p < (unsigned)CAND_CAP) {
                int j = i >> 2, ci = i & 3;
                unsigned idx = (unsigned)(4 * (t + THREADS * j) + ci);
                cand[p] = ((unsigned long long)__float_as_uint(val) << 12) | (unsigned long long)idx;
            }
        }
    }
    __syncthreads();

    // ---- keep decision + exp + sum ----
    float lsum = 0.0f;
#pragma unroll
    for (int i = 0; i < EPT; i++) {
        float val = v[i];
        int b = min((int)(val * (float)NBINS), NBINS - 1);
        bool keep;
        if ((unsigned)b > bstar) {
            keep = true;
        } else if ((unsigned)b < bstar) {
            keep = false;
        } else {
            int j = i >> 2, ci = i & 3;
            unsigned idx = (unsigned)(4 * (t + THREADS * j) + ci);
            unsigned long long key =
                ((unsigned long long)__float_as_uint(val) << 12) | (unsigned long long)idx;
            unsigned rk = 0;
            for (unsigned q = 0; q < ccnt; q++) rk += (cand[q] < key) ? 1u : 0u;
            keep = (rk >= rstar);   // rank within bin in stable-sort order
        }
        float e = keep ? __expf(val - m) : 0.0f;
        v[i] = e;
        lsum += e;
    }
#pragma unroll
    for (int o = 16; o; o >>= 1) lsum += __shfl_xor_sync(0xffffffffu, lsum, o);
    if (lane == 0) s_red[warp] = lsum;
    __syncthreads();
    if (t == 0) {
        float s = 0.0f;
#pragma unroll
        for (int i = 0; i < 8; i++) s += s_red[i];
        s_inv = 1.0f / s;
    }
    __syncthreads();
    const float inv = s_inv;

    // ---- scaled store ----
#pragma unroll
    for (int j = 0; j < VEC; j++) {
        float4 o4;
        o4.x = v[4 * j + 0] * inv;
        o4.y = v[4 * j + 1] * inv;
        o4.z = v[4 * j + 2] * inv;
        o4.w = v[4 * j + 3] * inv;
        out4[t + THREADS * j] = o4;
    }
}

} // anonymous namespace

extern "C" void kernel_launch(void* const* d_in, const int* in_sizes, int n_in,
                              void* d_out, int out_size)
{
    (void)n_in;
    const float* w = (const float*)d_in[0];
    float* out = (float*)d_out;
    int rows = out_size / N;           // 8192
    (void)in_sizes;
    wdrop_kernel<<<rows, THREADS>>>(w, out);
}

// round 2
// speedup vs baseline: 1.0283x; 1.0283x over previous
#include <cuda_runtime.h>
#include <cuda_bf16.h>
#include <stdint.h>

// WeightsDropout: per row of [8192,1,4096] f32, zero the 2048 smallest
// (stable-argsort tie-break by index), softmax over survivors.
//
// One CTA per row, row staged in SMEM (low regs -> high occupancy).
// Exact selection: count(v < 0.375) + 256-bin histogram over the window
// [0.375, 0.625) (boundary is at ~0.5 +- 16 sigma for uniform input);
// full-range 256-bin fallback keeps arbitrary inputs exact.
// Boundary-bin ties resolved by key = float_bits<<12 | index (== stable sort).

namespace {

constexpr int N        = 4096;
constexpr int KDROP    = 2048;
constexpr int THREADS  = 256;
constexpr int VEC      = N / 4 / THREADS;   // 4 float4 per thread
constexpr int NB       = 256;
constexpr int CAND_CAP = 256;

constexpr float WLO    = 0.375f;
constexpr float WHI    = 0.625f;
constexpr float WSCALE = 1024.0f;           // 256 bins over width 0.25

__device__ __forceinline__ int bin_of(float v, float lo, float sc) {
    // caller guarantees v >= lo
    return min((int)((v - lo) * sc), NB - 1);
}

__global__ __launch_bounds__(THREADS, 6)
void wdrop_kernel(const float* __restrict__ in, float* __restrict__ out)
{
    __shared__ float    vbuf[N];
    __shared__ unsigned hist[NB];
    __shared__ unsigned long long cand[CAND_CAP];
    __shared__ unsigned cand_n;
    __shared__ float    s_redf[8];
    __shared__ unsigned s_redu[8];
    __shared__ unsigned s_bin, s_rank, s_cnt, s_found, s_base;
    __shared__ float    s_max, s_inv;

    const int t    = threadIdx.x;
    const int lane = t & 31;
    const int warp = t >> 5;

    const long long row = blockIdx.x;
    const float4* __restrict__ in4  = reinterpret_cast<const float4*>(in  + row * (long long)N);
    float4*       __restrict__ out4 = reinterpret_cast<float4*>      (out + row * (long long)N);
    float4*                    vb4  = reinterpret_cast<float4*>(vbuf);

    hist[t] = 0u;                       // NB == THREADS
    if (t == 0) { cand_n = 0u; s_found = 0u; }
    __syncthreads();

    // ---- phase 1: gmem -> smem, max, count<WLO, window histogram ----
    float4 xs[VEC];
#pragma unroll
    for (int j = 0; j < VEC; j++) xs[j] = in4[t + THREADS * j];

    float vmax = -3.4e38f;
    unsigned below = 0;
#pragma unroll
    for (int j = 0; j < VEC; j++) {
        float4 x = xs[j];
        vb4[t + THREADS * j] = x;
        float vv[4] = {x.x, x.y, x.z, x.w};
#pragma unroll
        for (int c = 0; c < 4; c++) {
            float val = vv[c];
            vmax = fmaxf(vmax, val);
            below += (val < WLO) ? 1u : 0u;
            if (val >= WLO && val < WHI)
                atomicAdd(&hist[bin_of(val, WLO, WSCALE)], 1u);
        }
    }
#pragma unroll
    for (int o = 16; o; o >>= 1) {
        vmax   = fmaxf(vmax, __shfl_xor_sync(0xffffffffu, vmax, o));
        below += __shfl_xor_sync(0xffffffffu, below, o);
    }
    if (lane == 0) { s_redf[warp] = vmax; s_redu[warp] = below; }
    __syncthreads();
    if (t == 0) {
        float m = s_redf[0]; unsigned b = s_redu[0];
#pragma unroll
        for (int i = 1; i < 8; i++) { m = fmaxf(m, s_redf[i]); b += s_redu[i]; }
        s_max = m; s_base = b;
    }
    __syncthreads();

    // ---- scan window histogram (warp 0) ----
    if (warp == 0) {
        unsigned base = s_base;
        unsigned c8[8]; unsigned sum = 0;
#pragma unroll
        for (int i = 0; i < 8; i++) { c8[i] = hist[lane * 8 + i]; sum += c8[i]; }
        unsigned inc = sum;
#pragma unroll
        for (int o = 1; o < 32; o <<= 1) {
            unsigned nn = __shfl_up_sync(0xffffffffu, inc, o);
            if (lane >= o) inc += nn;
        }
        unsigned c = base + inc - sum;
#pragma unroll
        for (int i = 0; i < 8; i++) {
            unsigned cc = c8[i];
            if (c <= (unsigned)KDROP && (unsigned)KDROP < c + cc) {
                s_bin = (unsigned)(lane * 8 + i);
                s_rank = (unsigned)KDROP - c;
                s_cnt = cc;
                s_found = 1u;
            }
            c += cc;
        }
    }
    __syncthreads();

    // ---- fallback: boundary outside window (ultra-rare) ----
    float lo = WLO, sc = WSCALE, hiv = WHI;
    if (!s_found) {
        hist[t] = 0u;
        __syncthreads();
#pragma unroll
        for (int j = 0; j < VEC; j++) {
            float4 x = vb4[t + THREADS * j];
            float vv[4] = {x.x, x.y, x.z, x.w};
#pragma unroll
            for (int c = 0; c < 4; c++) {
                int b = max(min((int)(vv[c] * 256.0f), NB - 1), 0);
                atomicAdd(&hist[b], 1u);
            }
        }
        __syncthreads();
        if (warp == 0) {
            unsigned c8[8]; unsigned sum = 0;
#pragma unroll
            for (int i = 0; i < 8; i++) { c8[i] = hist[lane * 8 + i]; sum += c8[i]; }
            unsigned inc = sum;
#pragma unroll
            for (int o = 1; o < 32; o <<= 1) {
                unsigned nn = __shfl_up_sync(0xffffffffu, inc, o);
                if (lane >= o) inc += nn;
            }
            unsigned c = inc - sum;
#pragma unroll
            for (int i = 0; i < 8; i++) {
                unsigned cc = c8[i];
                if (c <= (unsigned)KDROP && (unsigned)KDROP < c + cc) {
                    s_bin = (unsigned)(lane * 8 + i);
                    s_rank = (unsigned)KDROP - c;
                    s_cnt = cc;
                }
                c += cc;
            }
        }
        lo = 0.0f; sc = 256.0f; hiv = 1e30f;
        __syncthreads();
    }

    const unsigned bstar = s_bin;
    const unsigned rstar = s_rank;
    const unsigned ccnt  = min(s_cnt, (unsigned)CAND_CAP);
    const float    m     = s_max;

    // ---- gather boundary-bin candidates ----
#pragma unroll
    for (int j = 0; j < VEC; j++) {
        float4 x = vb4[t + THREADS * j];
        float vv[4] = {x.x, x.y, x.z, x.w};
#pragma unroll
        for (int c = 0; c < 4; c++) {
            float val = vv[c];
            if (val >= lo && val < hiv) {
                if ((unsigned)bin_of(val, lo, sc) == bstar) {
                    unsigned p = atomicAdd(&cand_n, 1u);
                    if (p < (unsigned)CAND_CAP) {
                        unsigned idx = (unsigned)(4 * (t + THREADS * j) + c);
                        cand[p] = ((unsigned long long)__float_as_uint(val) << 12)
                                | (unsigned long long)idx;
                    }
                }
            }
        }
    }
    __syncthreads();

    // ---- keep decision + exp; e written back to vbuf ----
    float lsum = 0.0f;
#pragma unroll
    for (int j = 0; j < VEC; j++) {
        float4 x = vb4[t + THREADS * j];
        float vv[4] = {x.x, x.y, x.z, x.w};
        float ee[4];
#pragma unroll
        for (int c = 0; c < 4; c++) {
            float val = vv[c];
            bool keep;
            if (val >= hiv) {
                keep = true;
            } else if (val < lo) {
                keep = false;
            } else {
                unsigned b = (unsigned)bin_of(val, lo, sc);
                if (b > bstar) keep = true;
                else if (b < bstar) keep = false;
                else {
                    unsigned idx = (unsigned)(4 * (t + THREADS * j) + c);
                    unsigned long long key =
                        ((unsigned long long)__float_as_uint(val) << 12)
                      | (unsigned long long)idx;
                    unsigned rk = 0;
                    for (unsigned q = 0; q < ccnt; q++) rk += (cand[q] < key) ? 1u : 0u;
                    keep = (rk >= rstar);
                }
            }
            float e = keep ? __expf(val - m) : 0.0f;
            ee[c] = e;
            lsum += e;
        }
        float4 eo = {ee[0], ee[1], ee[2], ee[3]};
        vb4[t + THREADS * j] = eo;
    }
#pragma unroll
    for (int o = 16; o; o >>= 1) lsum += __shfl_xor_sync(0xffffffffu, lsum, o);
    if (lane == 0) s_redf[warp] = lsum;
    __syncthreads();
    if (t == 0) {
        float s = 0.0f;
#pragma unroll
        for (int i = 0; i < 8; i++) s += s_redf[i];
        s_inv = 1.0f / s;
    }
    __syncthreads();
    const float inv = s_inv;

    // ---- scaled store ----
#pragma unroll
    for (int j = 0; j < VEC; j++) {
        float4 e4 = vb4[t + THREADS * j];
        float4 o4 = {e4.x * inv, e4.y * inv, e4.z * inv, e4.w * inv};
        out4[t + THREADS * j] = o4;
    }
}

} // anonymous namespace

extern "C" void kernel_launch(void* const* d_in, const int* in_sizes, int n_in,
                              void* d_out, int out_size)
{
    (void)n_in; (void)in_sizes;
    const float* w = (const float*)d_in[0];
    float* outp = (float*)d_out;
    int rows = out_size / N;            // 8192
    wdrop_kernel<<<rows, THREADS>>>(w, outp);
}

// round 3
// speedup vs baseline: 1.1081x; 1.0776x over previous
#include <cuda_runtime.h>
#include <cuda_bf16.h>
#include <stdint.h>

// WeightsDropout: per row of [8192,1,4096] f32, zero the 2048 smallest
// (stable-argsort tie-break by index), softmax over survivors.
//
// One CTA (512 thr) per row; row lives in registers (2 float4/thread).
// Selection: count(v<0.375) + 256-bin histogram over [0.375,0.625)
// (boundary at 0.5 +- 16 sigma for uniform input; exact full-range
// fallback otherwise). Then compute the exact threshold KEY
// (float_bits<<12 | index == stable-sort order) whose global rank is
// KDROP; hot path is a single compare per element.

namespace {

constexpr int N        = 4096;
constexpr int KDROP    = 2048;
constexpr int THREADS  = 512;
constexpr int VEC      = N / 4 / THREADS;   // 2 float4 per thread
constexpr int NWARP    = THREADS / 32;      // 16
constexpr int NB       = 256;
constexpr int CAND_CAP = 256;

constexpr float WLO    = 0.375f;
constexpr float WHI    = 0.625f;
constexpr float WSCALE = 1024.0f;           // 256 bins over width 0.25

__device__ __forceinline__ int bin_of(float v, float lo, float sc) {
    return min((int)((v - lo) * sc), NB - 1);   // caller guarantees v >= lo
}

__global__ __launch_bounds__(THREADS, 3)
void wdrop_kernel(const float* __restrict__ in, float* __restrict__ out)
{
    __shared__ unsigned hist[NB];
    __shared__ unsigned long long cand[CAND_CAP];
    __shared__ unsigned cand_n;
    __shared__ float    s_redf[NWARP];
    __shared__ unsigned s_redu[NWARP];
    __shared__ unsigned s_bin, s_rank, s_found;
    __shared__ float    s_max, s_inv;
    __shared__ unsigned long long s_thr;

    const int t    = threadIdx.x;
    const int lane = t & 31;
    const int warp = t >> 5;

    const long long row = blockIdx.x;
    const float4* __restrict__ in4  = reinterpret_cast<const float4*>(in  + row * (long long)N);
    float4*       __restrict__ out4 = reinterpret_cast<float4*>      (out + row * (long long)N);

    if (t < NB) hist[t] = 0u;
    if (t == 0) { cand_n = 0u; s_found = 0u; }
    __syncthreads();

    // ---- load into registers; max, below-count, window histogram ----
    float4 xs[VEC];
#pragma unroll
    for (int j = 0; j < VEC; j++) xs[j] = in4[t + THREADS * j];

    float vmax = -3.4e38f;
    unsigned below = 0;
#pragma unroll
    for (int j = 0; j < VEC; j++) {
        float vv[4] = {xs[j].x, xs[j].y, xs[j].z, xs[j].w};
#pragma unroll
        for (int c = 0; c < 4; c++) {
            float val = vv[c];
            vmax = fmaxf(vmax, val);
            below += (val < WLO) ? 1u : 0u;
            if (val >= WLO && val < WHI)
                atomicAdd(&hist[bin_of(val, WLO, WSCALE)], 1u);
        }
    }
#pragma unroll
    for (int o = 16; o; o >>= 1) {
        vmax   = fmaxf(vmax, __shfl_xor_sync(0xffffffffu, vmax, o));
        below += __shfl_xor_sync(0xffffffffu, below, o);
    }
    if (lane == 0) { s_redf[warp] = vmax; s_redu[warp] = below; }
    __syncthreads();

    // ---- warp 0: combine reductions, scan histogram ----
    if (warp == 0) {
        float    m = (lane < NWARP) ? s_redf[lane] : -3.4e38f;
        unsigned b = (lane < NWARP) ? s_redu[lane] : 0u;
#pragma unroll
        for (int o = 16; o; o >>= 1) {
            m  = fmaxf(m, __shfl_xor_sync(0xffffffffu, m, o));
            b += __shfl_xor_sync(0xffffffffu, b, o);
        }
        if (lane == 0) s_max = m;

        unsigned c8[8]; unsigned sum = 0;
#pragma unroll
        for (int i = 0; i < 8; i++) { c8[i] = hist[lane * 8 + i]; sum += c8[i]; }
        unsigned inc = sum;
#pragma unroll
        for (int o = 1; o < 32; o <<= 1) {
            unsigned nn = __shfl_up_sync(0xffffffffu, inc, o);
            if (lane >= o) inc += nn;
        }
        unsigned c = b + inc - sum;
#pragma unroll
        for (int i = 0; i < 8; i++) {
            unsigned cc = c8[i];
            if (c <= (unsigned)KDROP && (unsigned)KDROP < c + cc) {
                s_bin = (unsigned)(lane * 8 + i);
                s_rank = (unsigned)KDROP - c;
                s_found = 1u;
            }
            c += cc;
        }
    }
    __syncthreads();

    // ---- fallback: boundary outside window (ultra-rare, still exact) ----
    float lo = WLO, sc = WSCALE, hiv = WHI;
    if (!s_found) {
        if (t < NB) hist[t] = 0u;
        __syncthreads();
#pragma unroll
        for (int j = 0; j < VEC; j++) {
            float vv[4] = {xs[j].x, xs[j].y, xs[j].z, xs[j].w};
#pragma unroll
            for (int c = 0; c < 4; c++) {
                int b = max(min((int)(vv[c] * 256.0f), NB - 1), 0);
                atomicAdd(&hist[b], 1u);
            }
        }
        __syncthreads();
        if (warp == 0) {
            unsigned c8[8]; unsigned sum = 0;
#pragma unroll
            for (int i = 0; i < 8; i++) { c8[i] = hist[lane * 8 + i]; sum += c8[i]; }
            unsigned inc = sum;
#pragma unroll
            for (int o = 1; o < 32; o <<= 1) {
                unsigned nn = __shfl_up_sync(0xffffffffu, inc, o);
                if (lane >= o) inc += nn;
            }
            unsigned c = inc - sum;
#pragma unroll
            for (int i = 0; i < 8; i++) {
                unsigned cc = c8[i];
                if (c <= (unsigned)KDROP && (unsigned)KDROP < c + cc) {
                    s_bin = (unsigned)(lane * 8 + i);
                    s_rank = (unsigned)KDROP - c;
                }
                c += cc;
            }
        }
        lo = 0.0f; sc = 256.0f; hiv = 1e30f;
        __syncthreads();
    }

    const unsigned bstar = s_bin;
    const unsigned rstar = s_rank;

    // ---- gather boundary-bin candidates (keys) ----
#pragma unroll
    for (int j = 0; j < VEC; j++) {
        float vv[4] = {xs[j].x, xs[j].y, xs[j].z, xs[j].w};
#pragma unroll
        for (int c = 0; c < 4; c++) {
            float val = vv[c];
            if (val >= lo && val < hiv && (unsigned)bin_of(val, lo, sc) == bstar) {
                unsigned p = atomicAdd(&cand_n, 1u);
                if (p < (unsigned)CAND_CAP) {
                    unsigned idx = (unsigned)(4 * (t + THREADS * j) + c);
                    cand[p] = ((unsigned long long)__float_as_uint(val) << 12)
                            | (unsigned long long)idx;
                }
            }
        }
    }
    __syncthreads();

    // ---- warp 0: threshold key = candidate with in-bin rank rstar ----
    if (warp == 0) {
        unsigned c = min(cand_n, (unsigned)CAND_CAP);
        for (unsigned base = 0; base < c; base += 32) {
            unsigned q = base + lane;
            if (q < c) {
                unsigned long long k = cand[q];
                unsigned rk = 0;
                for (unsigned i = 0; i < c; i++) rk += (cand[i] < k) ? 1u : 0u;
                if (rk == rstar) s_thr = k;   // global rank == KDROP
            }
        }
    }
    __syncthreads();

    const unsigned long long thr = s_thr;
    const float    thr_val = __uint_as_float((unsigned)(thr >> 12));
    const unsigned thr_idx = (unsigned)(thr & 0xFFFull);
    const float    m       = s_max;

    // ---- hot path: single-compare keep, exp, sum ----
    float lsum = 0.0f;
#pragma unroll
    for (int j = 0; j < VEC; j++) {
        float vv[4] = {xs[j].x, xs[j].y, xs[j].z, xs[j].w};
        float ee[4];
#pragma unroll
        for (int c = 0; c < 4; c++) {
            float val = vv[c];
            unsigned idx = (unsigned)(4 * (t + THREADS * j) + c);
            bool keep = (val > thr_val) || (val == thr_val && idx >= thr_idx);
            float e = keep ? __expf(val - m) : 0.0f;
            ee[c] = e;
            lsum += e;
        }
        xs[j].x = ee[0]; xs[j].y = ee[1]; xs[j].z = ee[2]; xs[j].w = ee[3];
    }
#pragma unroll
    for (int o = 16; o; o >>= 1) lsum += __shfl_xor_sync(0xffffffffu, lsum, o);
    if (lane == 0) s_redf[warp] = lsum;
    __syncthreads();
    if (warp == 0) {
        float s = (lane < NWARP) ? s_redf[lane] : 0.0f;
#pragma unroll
        for (int o = 16; o; o >>= 1) s += __shfl_xor_sync(0xffffffffu, s, o);
        if (lane == 0) s_inv = 1.0f / s;
    }
    __syncthreads();
    const float inv = s_inv;

    // ---- scaled store straight from registers ----
#pragma unroll
    for (int j = 0; j < VEC; j++) {
        float4 o4 = {xs[j].x * inv, xs[j].y * inv, xs[j].z * inv, xs[j].w * inv};
        out4[t + THREADS * j] = o4;
    }
}

} // anonymous namespace

extern "C" void kernel_launch(void* const* d_in, const int* in_sizes, int n_in,
                              void* d_out, int out_size)
{
    (void)n_in; (void)in_sizes;
    const float* w = (const float*)d_in[0];
    float* outp = (float*)d_out;
    int rows = out_size / N;            // 8192
    wdrop_kernel<<<rows, THREADS>>>(w, outp);
}